// round 2
// baseline (speedup 1.0000x reference)
#include <cuda_runtime.h>
#include <cuda_bf16.h>
#include <cstdint>

// Problem constants
#define NB   4
#define LL   2048
#define EE   1024
#define HID  1024
#define HEADS 16
#define DH   64
#define MROWS (NB * LL)          // 8192
#define NPAIR (NB * HEADS)       // 64

// Scratch (static device globals — no allocation allowed)
__device__ float g_Q[MROWS * HID];
__device__ float g_K[MROWS * HID];
__device__ float g_V[MROWS * HID];   // becomes Y in-place after apply_diag
__device__ float g_diag[NPAIR * LL];

// ---------------------------------------------------------------------------
// GEMM: C[M,N] = A[M,K] @ B[K,N] + bias[N], all row-major fp32.
// 128x128 block tile, BK=16, 256 threads, 8x8 per thread.
// ---------------------------------------------------------------------------
#define BM 128
#define BN 128
#define BK 16
#define TM 8
#define TN 8

__global__ __launch_bounds__(256) void gemm_bias_kernel(
    const float* __restrict__ A, const float* __restrict__ B,
    const float* __restrict__ bias, float* __restrict__ C,
    int M, int N, int K)
{
    __shared__ float As[BK][BM + 4];   // transposed A tile: As[k][m]
    __shared__ float Bs[BK][BN + 4];   // Bs[k][n]

    const int t  = threadIdx.x;
    const int bm = blockIdx.y * BM;
    const int bn = blockIdx.x * BN;
    const int tx = t & 15;     // n direction
    const int ty = t >> 4;     // m direction

    float acc[TM][TN];
    #pragma unroll
    for (int i = 0; i < TM; i++)
        #pragma unroll
        for (int j = 0; j < TN; j++) acc[i][j] = 0.f;

    for (int k0 = 0; k0 < K; k0 += BK) {
        // Load A tile (128 rows x 16 k) -> store transposed As[k][m]
        #pragma unroll
        for (int i = 0; i < 2; i++) {
            int idx = t * 2 + i;          // 0..511
            int row = idx >> 2;           // 0..127
            int kq  = idx & 3;            // 0..3
            float4 v = *reinterpret_cast<const float4*>(
                &A[(size_t)(bm + row) * K + k0 + kq * 4]);
            As[kq * 4 + 0][row] = v.x;
            As[kq * 4 + 1][row] = v.y;
            As[kq * 4 + 2][row] = v.z;
            As[kq * 4 + 3][row] = v.w;
        }
        // Load B tile (16 k x 128 n)
        #pragma unroll
        for (int i = 0; i < 2; i++) {
            int idx = t * 2 + i;          // 0..511
            int row = idx >> 5;           // k 0..15
            int nq  = idx & 31;           // 0..31
            float4 v = *reinterpret_cast<const float4*>(
                &B[(size_t)(k0 + row) * N + bn + nq * 4]);
            *reinterpret_cast<float4*>(&Bs[row][nq * 4]) = v;
        }
        __syncthreads();

        #pragma unroll
        for (int k = 0; k < BK; k++) {
            float a[TM], b[TN];
            #pragma unroll
            for (int i = 0; i < TM; i++) a[i] = As[k][ty * TM + i];
            #pragma unroll
            for (int j = 0; j < TN; j++) b[j] = Bs[k][tx * TN + j];
            #pragma unroll
            for (int i = 0; i < TM; i++)
                #pragma unroll
                for (int j = 0; j < TN; j++)
                    acc[i][j] += a[i] * b[j];
        }
        __syncthreads();
    }

    // Epilogue with bias
    #pragma unroll
    for (int i = 0; i < TM; i++) {
        size_t row = (size_t)(bm + ty * TM + i);
        #pragma unroll
        for (int j = 0; j < TN; j += 4) {
            int col = bn + tx * TN + j;
            float4 v;
            v.x = acc[i][j + 0] + bias[col + 0];
            v.y = acc[i][j + 1] + bias[col + 1];
            v.z = acc[i][j + 2] + bias[col + 2];
            v.w = acc[i][j + 3] + bias[col + 3];
            *reinterpret_cast<float4*>(&C[row * N + col]) = v;
        }
    }
}

// ---------------------------------------------------------------------------
// Score/diag kernel: for each (n,h) pair p, head matrices are contiguous
// 2048x64 fp32 blocks. Compute diag[p][b] = exp(s[b,b]) / sum_a exp(s[a,b])
// with s[a,b] = (Qh[a,:] . Kh[b,:]) / 1024.
// One block = 128 columns (each thread owns one column, K row in registers).
// Q rows streamed through smem in chunks of 64 (broadcast reads).
// ---------------------------------------------------------------------------
__global__ __launch_bounds__(128) void score_diag_kernel(
    const float* __restrict__ Q, const float* __restrict__ Kmat,
    float* __restrict__ diag)
{
    __shared__ float4 Qs[64][16];

    const int p = blockIdx.y;                       // pair 0..63
    const float* Qh = Q    + (size_t)p * LL * DH;
    const float* Kh = Kmat + (size_t)p * LL * DH;
    const int t = threadIdx.x;
    const int b = blockIdx.x * 128 + t;             // column owned by thread

    float4 kreg[16];
    const float4* krow = reinterpret_cast<const float4*>(Kh + (size_t)b * DH);
    #pragma unroll
    for (int i = 0; i < 16; i++) kreg[i] = krow[i];

    float csum = 0.f;
    float dval = 0.f;

    for (int a0 = 0; a0 < LL; a0 += 64) {
        // Cooperative load of 64 Q rows (1024 float4, 8 per thread, coalesced)
        #pragma unroll
        for (int i = 0; i < 8; i++) {
            int idx = t + i * 128;
            int row = idx >> 4;
            int xq  = idx & 15;
            Qs[row][xq] = reinterpret_cast<const float4*>(
                Qh + (size_t)(a0 + row) * DH)[xq];
        }
        __syncthreads();

        #pragma unroll 4
        for (int aa = 0; aa < 64; aa++) {
            float dot = 0.f;
            #pragma unroll
            for (int xq = 0; xq < 16; xq++) {
                float4 q = Qs[aa][xq];
                dot += q.x * kreg[xq].x;
                dot += q.y * kreg[xq].y;
                dot += q.z * kreg[xq].z;
                dot += q.w * kreg[xq].w;
            }
            float e = __expf(dot * (1.0f / 1024.0f));
            csum += e;
            if (a0 + aa == b) dval = e;
        }
        __syncthreads();
    }

    diag[(size_t)p * LL + b] = dval / csum;
}

// ---------------------------------------------------------------------------
// Apply diagonal: Y[n,l,e] = V[n,l,e] * diag[n, l/128, (l%128)*16 + e/64]
// In-place on g_V. e/64 is constant within a float4, so vectorize by 4.
// ---------------------------------------------------------------------------
__global__ __launch_bounds__(256) void apply_diag_kernel(
    float* __restrict__ V, const float* __restrict__ diag)
{
    size_t i = (size_t)blockIdx.x * blockDim.x + threadIdx.x;  // float4 index
    const size_t total4 = (size_t)NB * LL * HID / 4;
    if (i >= total4) return;
    size_t elem = i * 4;
    int e = (int)(elem & (HID - 1));
    int l = (int)((elem >> 10) & (LL - 1));
    int n = (int)(elem >> 21);                 // / (LL*HID) = / 2^21
    int h = l >> 7;
    int a = ((l & 127) << 4) | (e >> 6);
    float dd = diag[((size_t)(n * HEADS + h)) * LL + a];
    float4 v = reinterpret_cast<float4*>(V)[i];
    v.x *= dd; v.y *= dd; v.z *= dd; v.w *= dd;
    reinterpret_cast<float4*>(V)[i] = v;
}

// ---------------------------------------------------------------------------
// Launch
// ---------------------------------------------------------------------------
extern "C" void kernel_launch(void* const* d_in, const int* in_sizes, int n_in,
                              void* d_out, int out_size)
{
    const float* X  = (const float*)d_in[0];
    const float* Wq = (const float*)d_in[1];
    const float* bq = (const float*)d_in[2];
    const float* Wk = (const float*)d_in[3];
    const float* bk = (const float*)d_in[4];
    const float* Wv = (const float*)d_in[5];
    const float* bv = (const float*)d_in[6];
    const float* Wo = (const float*)d_in[7];
    const float* bo = (const float*)d_in[8];
    float* out = (float*)d_out;

    float *Q, *K, *V, *dg;
    cudaGetSymbolAddress((void**)&Q,  g_Q);
    cudaGetSymbolAddress((void**)&K,  g_K);
    cudaGetSymbolAddress((void**)&V,  g_V);
    cudaGetSymbolAddress((void**)&dg, g_diag);

    dim3 ggrid(HID / BN, MROWS / BM);   // (8, 64)

    gemm_bias_kernel<<<ggrid, 256>>>(X, Wq, bq, Q, MROWS, HID, EE);
    gemm_bias_kernel<<<ggrid, 256>>>(X, Wk, bk, K, MROWS, HID, EE);
    gemm_bias_kernel<<<ggrid, 256>>>(X, Wv, bv, V, MROWS, HID, EE);

    dim3 sgrid(LL / 128, NPAIR);        // (16, 64)
    score_diag_kernel<<<sgrid, 128>>>(Q, K, dg);

    size_t total4 = (size_t)NB * LL * HID / 4;
    apply_diag_kernel<<<(unsigned)((total4 + 255) / 256), 256>>>(V, dg);

    gemm_bias_kernel<<<ggrid, 256>>>(V, Wo, bo, out, MROWS, HID, HID);
}

// round 6
// speedup vs baseline: 3.0474x; 3.0474x over previous
#include <cuda_runtime.h>
#include <cstdint>

// Problem constants
#define NB    4
#define LL    2048
#define EE    1024
#define HID   1024
#define HEADS 16
#define DH    64
#define MROWS 8192
#define NPAIR 64

// Scratch (static device globals)
__device__ float g_Q[MROWS * HID];
__device__ float g_K[MROWS * HID];
__device__ float g_V[MROWS * HID];
__device__ float g_diagE[NPAIR * LL];
__device__ float g_colsum[NPAIR * LL];

// ---------------------------------------------------------------------------
__device__ __forceinline__ uint32_t f2tf32(float x) {
    uint32_t r;
    asm("cvt.rna.tf32.f32 %0, %1;" : "=r"(r) : "f"(x));
    return r;
}

__device__ __forceinline__ void mma_tf32(float c[4], const uint32_t a[4], const uint32_t b[2]) {
    asm volatile(
        "mma.sync.aligned.m16n8k8.row.col.f32.tf32.tf32.f32 "
        "{%0,%1,%2,%3}, {%4,%5,%6,%7}, {%8,%9}, {%0,%1,%2,%3};\n"
        : "+f"(c[0]), "+f"(c[1]), "+f"(c[2]), "+f"(c[3])
        : "r"(a[0]), "r"(a[1]), "r"(a[2]), "r"(a[3]), "r"(b[0]), "r"(b[1]));
}

__device__ __forceinline__ float4 tf4(float4 v) {
    float4 w;
    w.x = __uint_as_float(f2tf32(v.x));
    w.y = __uint_as_float(f2tf32(v.y));
    w.z = __uint_as_float(f2tf32(v.z));
    w.w = __uint_as_float(f2tf32(v.w));
    return w;
}

// ---------------------------------------------------------------------------
// Tensor-core GEMM: C[M,N] = A[M,K] @ B[K,N] + bias, fp32 in/out, tf32 mma.
// Block tile 256x128, BK=16, 8 warps (4m x 2n), warp tile 64x64.
// ---------------------------------------------------------------------------
#define GBM 256
#define GBN 128
#define GBK 16
#define ASTR 20     // As row stride (banks: 20r+c -> 4-spread, conflict-free)
#define BSTR 136    // Bs row stride (banks: 8c+r, conflict-free)

__global__ __launch_bounds__(256, 1) void gemm_tc(
    const float* __restrict__ A, const float* __restrict__ B,
    const float* __restrict__ bias, float* __restrict__ C,
    int M, int N, int K)
{
    __shared__ float As[GBM * ASTR];   // [row][k]
    __shared__ float Bs[GBK * BSTR];   // [k][n]

    const int t    = threadIdx.x;
    const int lane = t & 31, wid = t >> 5;
    const int wm = wid & 3, wn = wid >> 2;
    const int r = lane >> 2, cq = lane & 3;
    const int bm = blockIdx.y * GBM, bn = blockIdx.x * GBN;

    float acc[4][8][4];
    #pragma unroll
    for (int mt = 0; mt < 4; mt++)
        #pragma unroll
        for (int nt = 0; nt < 8; nt++)
            #pragma unroll
            for (int j = 0; j < 4; j++) acc[mt][nt][j] = 0.f;

    int arow[4], aq[4], brow[2], bq[2];
    #pragma unroll
    for (int i = 0; i < 4; i++) { int idx = t + i * 256; arow[i] = idx >> 2; aq[i] = idx & 3; }
    #pragma unroll
    for (int i = 0; i < 2; i++) { int idx = t + i * 256; brow[i] = idx >> 5; bq[i] = idx & 31; }

    float4 pa[4], pb[2];

    // Stage k-tile 0
    #pragma unroll
    for (int i = 0; i < 4; i++)
        pa[i] = *reinterpret_cast<const float4*>(&A[(size_t)(bm + arow[i]) * K + aq[i] * 4]);
    #pragma unroll
    for (int i = 0; i < 2; i++)
        pb[i] = *reinterpret_cast<const float4*>(&B[(size_t)brow[i] * N + bn + bq[i] * 4]);
    #pragma unroll
    for (int i = 0; i < 4; i++)
        *reinterpret_cast<float4*>(&As[arow[i] * ASTR + aq[i] * 4]) = tf4(pa[i]);
    #pragma unroll
    for (int i = 0; i < 2; i++)
        *reinterpret_cast<float4*>(&Bs[brow[i] * BSTR + bq[i] * 4]) = tf4(pb[i]);
    __syncthreads();

    const int KT = K / GBK;
    for (int kt = 0; kt < KT; kt++) {
        if (kt + 1 < KT) {
            int k0 = (kt + 1) * GBK;
            #pragma unroll
            for (int i = 0; i < 4; i++)
                pa[i] = *reinterpret_cast<const float4*>(&A[(size_t)(bm + arow[i]) * K + k0 + aq[i] * 4]);
            #pragma unroll
            for (int i = 0; i < 2; i++)
                pb[i] = *reinterpret_cast<const float4*>(&B[(size_t)(k0 + brow[i]) * N + bn + bq[i] * 4]);
        }

        #pragma unroll
        for (int kk = 0; kk < 2; kk++) {
            const int kb = kk * 8;
            uint32_t af[4][4], bf[8][2];
            #pragma unroll
            for (int mt = 0; mt < 4; mt++) {
                int rb = wm * 64 + mt * 16;
                af[mt][0] = __float_as_uint(As[(rb + r) * ASTR + kb + cq]);
                af[mt][1] = __float_as_uint(As[(rb + 8 + r) * ASTR + kb + cq]);
                af[mt][2] = __float_as_uint(As[(rb + r) * ASTR + kb + 4 + cq]);
                af[mt][3] = __float_as_uint(As[(rb + 8 + r) * ASTR + kb + 4 + cq]);
            }
            #pragma unroll
            for (int nt = 0; nt < 8; nt++) {
                int cb = wn * 64 + nt * 8 + r;
                bf[nt][0] = __float_as_uint(Bs[(kb + cq) * BSTR + cb]);
                bf[nt][1] = __float_as_uint(Bs[(kb + 4 + cq) * BSTR + cb]);
            }
            #pragma unroll
            for (int mt = 0; mt < 4; mt++)
                #pragma unroll
                for (int nt = 0; nt < 8; nt++)
                    mma_tf32(acc[mt][nt], af[mt], bf[nt]);
        }
        __syncthreads();

        if (kt + 1 < KT) {
            #pragma unroll
            for (int i = 0; i < 4; i++)
                *reinterpret_cast<float4*>(&As[arow[i] * ASTR + aq[i] * 4]) = tf4(pa[i]);
            #pragma unroll
            for (int i = 0; i < 2; i++)
                *reinterpret_cast<float4*>(&Bs[brow[i] * BSTR + bq[i] * 4]) = tf4(pb[i]);
        }
        __syncthreads();
    }

    // Epilogue with bias
    #pragma unroll
    for (int mt = 0; mt < 4; mt++) {
        int row0 = bm + wm * 64 + mt * 16 + r;
        #pragma unroll
        for (int nt = 0; nt < 8; nt++) {
            int col = bn + wn * 64 + nt * 8 + cq * 2;
            float b0 = bias[col], b1 = bias[col + 1];
            float2 v0 = make_float2(acc[mt][nt][0] + b0, acc[mt][nt][1] + b1);
            float2 v1 = make_float2(acc[mt][nt][2] + b0, acc[mt][nt][3] + b1);
            *reinterpret_cast<float2*>(&C[(size_t)row0 * N + col]) = v0;
            *reinterpret_cast<float2*>(&C[(size_t)(row0 + 8) * N + col]) = v1;
        }
    }
}

// ---------------------------------------------------------------------------
// Tensor-core score kernel. Per (pair p, 128-column block):
//   keep K-tile (128 cols x 64) in smem; stream Q in 128-row tiles;
//   S = Q K^T via tf32 mma; e = exp(S/1024); accumulate column sums in regs;
//   capture diagonal elements. diag/colsum written separately; division is
//   folded into apply_diag.
// 8 warps (4a x 2b), warp tile 32(a) x 64(b).
// ---------------------------------------------------------------------------
#define SSTR 68

__global__ __launch_bounds__(256, 1) void score_diag_tc(
    const float* __restrict__ Q, const float* __restrict__ Km,
    float* __restrict__ diagE, float* __restrict__ colsumG)
{
    extern __shared__ float sm[];
    float* Ks   = sm;                   // 128 x SSTR
    float* Qs   = sm + 128 * SSTR;      // 128 x SSTR
    float* csum = sm + 2 * 128 * SSTR;  // 128

    const int t    = threadIdx.x;
    const int lane = t & 31, wid = t >> 5;
    const int wm = wid & 3, wn = wid >> 2;
    const int r = lane >> 2, cq = lane & 3;

    const int p  = blockIdx.y;
    const int bn = blockIdx.x * 128;
    const float* Qh = Q  + (size_t)p * LL * DH;
    const float* Kh = Km + (size_t)p * LL * DH;

    // Load K tile: rows bn..bn+127, 64 floats each (tf32-rounded)
    #pragma unroll
    for (int i = 0; i < 8; i++) {
        int idx = t + i * 256;
        int row = idx >> 4, q = idx & 15;
        float4 v = *reinterpret_cast<const float4*>(&Kh[(size_t)(bn + row) * DH + q * 4]);
        *reinterpret_cast<float4*>(&Ks[row * SSTR + q * 4]) = tf4(v);
    }
    __syncthreads();

    float partial[8][2];
    #pragma unroll
    for (int nt = 0; nt < 8; nt++) { partial[nt][0] = 0.f; partial[nt][1] = 0.f; }

    const float S = 1.0f / 1024.0f;

    for (int a0 = 0; a0 < LL; a0 += 128) {
        // Load Q tile
        #pragma unroll
        for (int i = 0; i < 8; i++) {
            int idx = t + i * 256;
            int row = idx >> 4, q = idx & 15;
            float4 v = *reinterpret_cast<const float4*>(&Qh[(size_t)(a0 + row) * DH + q * 4]);
            *reinterpret_cast<float4*>(&Qs[row * SSTR + q * 4]) = tf4(v);
        }
        __syncthreads();

        float acc[2][8][4];
        #pragma unroll
        for (int mt = 0; mt < 2; mt++)
            #pragma unroll
            for (int nt = 0; nt < 8; nt++)
                #pragma unroll
                for (int j = 0; j < 4; j++) acc[mt][nt][j] = 0.f;

        #pragma unroll
        for (int kk = 0; kk < 8; kk++) {
            const int kb = kk * 8;
            uint32_t af[2][4], bf[8][2];
            #pragma unroll
            for (int mt = 0; mt < 2; mt++) {
                int rb = wm * 32 + mt * 16;
                af[mt][0] = __float_as_uint(Qs[(rb + r) * SSTR + kb + cq]);
                af[mt][1] = __float_as_uint(Qs[(rb + 8 + r) * SSTR + kb + cq]);
                af[mt][2] = __float_as_uint(Qs[(rb + r) * SSTR + kb + 4 + cq]);
                af[mt][3] = __float_as_uint(Qs[(rb + 8 + r) * SSTR + kb + 4 + cq]);
            }
            #pragma unroll
            for (int nt = 0; nt < 8; nt++) {
                int cb = wn * 64 + nt * 8 + r;
                bf[nt][0] = __float_as_uint(Ks[cb * SSTR + kb + cq]);
                bf[nt][1] = __float_as_uint(Ks[cb * SSTR + kb + 4 + cq]);
            }
            #pragma unroll
            for (int mt = 0; mt < 2; mt++)
                #pragma unroll
                for (int nt = 0; nt < 8; nt++)
                    mma_tf32(acc[mt][nt], af[mt], bf[nt]);
        }

        // exp + accumulate column sums; capture diagonal on the diagonal block
        const bool diagblk = (a0 == bn);
        #pragma unroll
        for (int mt = 0; mt < 2; mt++) {
            int arow0 = wm * 32 + mt * 16 + r;
            #pragma unroll
            for (int nt = 0; nt < 8; nt++) {
                #pragma unroll
                for (int j = 0; j < 2; j++) {
                    int bcol = wn * 64 + nt * 8 + cq * 2 + j;
                    float e0 = __expf(acc[mt][nt][j] * S);       // row arow0
                    float e1 = __expf(acc[mt][nt][2 + j] * S);   // row arow0 + 8
                    partial[nt][j] += e0 + e1;
                    if (diagblk) {
                        if (arow0 == bcol)     diagE[(size_t)p * LL + bn + bcol] = e0;
                        if (arow0 + 8 == bcol) diagE[(size_t)p * LL + bn + bcol] = e1;
                    }
                }
            }
        }
        __syncthreads();
    }

    // Reduce partial colsums over the 8 row-groups within the warp
    #pragma unroll
    for (int nt = 0; nt < 8; nt++)
        #pragma unroll
        for (int j = 0; j < 2; j++) {
            float v = partial[nt][j];
            v += __shfl_xor_sync(0xFFFFFFFF, v, 4);
            v += __shfl_xor_sync(0xFFFFFFFF, v, 8);
            v += __shfl_xor_sync(0xFFFFFFFF, v, 16);
            partial[nt][j] = v;
        }

    if (t < 128) csum[t] = 0.f;
    __syncthreads();
    if (r == 0) {
        #pragma unroll
        for (int nt = 0; nt < 8; nt++)
            #pragma unroll
            for (int j = 0; j < 2; j++)
                atomicAdd(&csum[wn * 64 + nt * 8 + cq * 2 + j], partial[nt][j]);
    }
    __syncthreads();
    if (t < 128) colsumG[(size_t)p * LL + bn + t] = csum[t];
}

// ---------------------------------------------------------------------------
// Apply diagonal: Y[n,l,e] = V[n,l,e] * diagE[...]/colsum[...]
// ---------------------------------------------------------------------------
__global__ __launch_bounds__(256) void apply_diag_kernel(
    float* __restrict__ V, const float* __restrict__ diagE,
    const float* __restrict__ colsum)
{
    size_t i = (size_t)blockIdx.x * blockDim.x + threadIdx.x;  // float4 index
    const size_t total4 = (size_t)NB * LL * HID / 4;
    if (i >= total4) return;
    size_t elem = i * 4;
    int e = (int)(elem & (HID - 1));
    int l = (int)((elem >> 10) & (LL - 1));
    int n = (int)(elem >> 21);
    int h = l >> 7;
    int a = ((l & 127) << 4) | (e >> 6);
    size_t didx = ((size_t)(n * HEADS + h)) * LL + a;
    float dd = diagE[didx] / colsum[didx];
    float4 v = reinterpret_cast<float4*>(V)[i];
    v.x *= dd; v.y *= dd; v.z *= dd; v.w *= dd;
    reinterpret_cast<float4*>(V)[i] = v;
}

// ---------------------------------------------------------------------------
extern "C" void kernel_launch(void* const* d_in, const int* in_sizes, int n_in,
                              void* d_out, int out_size)
{
    const float* X  = (const float*)d_in[0];
    const float* Wq = (const float*)d_in[1];
    const float* bq = (const float*)d_in[2];
    const float* Wk = (const float*)d_in[3];
    const float* bk = (const float*)d_in[4];
    const float* Wv = (const float*)d_in[5];
    const float* bv = (const float*)d_in[6];
    const float* Wo = (const float*)d_in[7];
    const float* bo = (const float*)d_in[8];
    float* out = (float*)d_out;

    float *Q, *K, *V, *dgE, *cs;
    cudaGetSymbolAddress((void**)&Q,   g_Q);
    cudaGetSymbolAddress((void**)&K,   g_K);
    cudaGetSymbolAddress((void**)&V,   g_V);
    cudaGetSymbolAddress((void**)&dgE, g_diagE);
    cudaGetSymbolAddress((void**)&cs,  g_colsum);

    const int score_smem = (2 * 128 * SSTR + 128) * sizeof(float);
    static int attr_done = 0;
    if (!attr_done) {
        cudaFuncSetAttribute(score_diag_tc,
                             cudaFuncAttributeMaxDynamicSharedMemorySize, score_smem);
        attr_done = 1;
    }

    dim3 ggrid(HID / GBN, MROWS / GBM);   // (8, 32)

    gemm_tc<<<ggrid, 256>>>(X, Wq, bq, Q, MROWS, HID, EE);
    gemm_tc<<<ggrid, 256>>>(X, Wk, bk, K, MROWS, HID, EE);
    gemm_tc<<<ggrid, 256>>>(X, Wv, bv, V, MROWS, HID, EE);

    dim3 sgrid(LL / 128, NPAIR);          // (16, 64)
    score_diag_tc<<<sgrid, 256, score_smem>>>(Q, K, dgE, cs);

    size_t total4 = (size_t)NB * LL * HID / 4;
    apply_diag_kernel<<<(unsigned)((total4 + 255) / 256), 256>>>(V, dgE, cs);

    gemm_tc<<<ggrid, 256>>>(V, Wo, bo, out, MROWS, HID, HID);
}

// round 7
// speedup vs baseline: 3.0889x; 1.0136x over previous
#include <cuda_runtime.h>
#include <cstdint>

// Problem constants
#define NB    4
#define LL    2048
#define EE    1024
#define HID   1024
#define HEADS 16
#define DH    64
#define MROWS 8192
#define NPAIR 64
#define RBLK  16            // row-blocks in score kernel (2048/128)

// Scratch (static device globals)
__device__ float g_Q[MROWS * HID];
__device__ float g_K[MROWS * HID];
__device__ float g_V[MROWS * HID];
__device__ float g_diagE[NPAIR * LL];
__device__ float g_part[RBLK * NPAIR * LL];   // per-rowblock column partial sums
__device__ float g_diag[NPAIR * LL];          // final diagE / colsum

// ---------------------------------------------------------------------------
__device__ __forceinline__ uint32_t f2tf32(float x) {
    uint32_t r;
    asm("cvt.rna.tf32.f32 %0, %1;" : "=r"(r) : "f"(x));
    return r;
}

__device__ __forceinline__ void mma_tf32(float c[4], const uint32_t a[4], const uint32_t b[2]) {
    asm volatile(
        "mma.sync.aligned.m16n8k8.row.col.f32.tf32.tf32.f32 "
        "{%0,%1,%2,%3}, {%4,%5,%6,%7}, {%8,%9}, {%0,%1,%2,%3};\n"
        : "+f"(c[0]), "+f"(c[1]), "+f"(c[2]), "+f"(c[3])
        : "r"(a[0]), "r"(a[1]), "r"(a[2]), "r"(a[3]), "r"(b[0]), "r"(b[1]));
}

__device__ __forceinline__ float4 tf4(float4 v) {
    float4 w;
    w.x = __uint_as_float(f2tf32(v.x));
    w.y = __uint_as_float(f2tf32(v.y));
    w.z = __uint_as_float(f2tf32(v.z));
    w.w = __uint_as_float(f2tf32(v.w));
    return w;
}

// ---------------------------------------------------------------------------
// Tensor-core GEMM body: C[M,N] = (scale ? diag-scaled A : A)[M,K] @ B + bias.
// Block tile 256x128, BK=16, 8 warps (4m x 2n), warp tile 64x64.
// When scale != nullptr, each loaded A element at (row l, col k) is multiplied
// by scale[(n*HEADS+h)*LL + a] with n=l>>11, h=(l&2047)>>7,
// a=(((l&2047)&127)<<4)|(k>>6)  (constant within a float4).
// ---------------------------------------------------------------------------
#define GBM 256
#define GBN 128
#define GBK 16
#define ASTR 20
#define BSTR 136

__device__ __forceinline__ float scale_of(const float* scale, int row, int k) {
    int lr = row & (LL - 1);
    int n  = row >> 11;
    int h  = lr >> 7;
    int a  = ((lr & 127) << 4) | (k >> 6);
    return scale[((size_t)(n * HEADS + h)) * LL + a];
}

__device__ __forceinline__ void gemm_body(
    const float* __restrict__ A, const float* __restrict__ B,
    const float* __restrict__ bias, float* __restrict__ C,
    const float* __restrict__ scale, int N, int K, int bm, int bn)
{
    __shared__ float As[GBM * ASTR];
    __shared__ float Bs[GBK * BSTR];

    const int t    = threadIdx.x;
    const int lane = t & 31, wid = t >> 5;
    const int wm = wid & 3, wn = wid >> 2;
    const int r = lane >> 2, cq = lane & 3;

    float acc[4][8][4];
    #pragma unroll
    for (int mt = 0; mt < 4; mt++)
        #pragma unroll
        for (int nt = 0; nt < 8; nt++)
            #pragma unroll
            for (int j = 0; j < 4; j++) acc[mt][nt][j] = 0.f;

    int arow[4], aq[4], brow[2], bq[2];
    #pragma unroll
    for (int i = 0; i < 4; i++) { int idx = t + i * 256; arow[i] = idx >> 2; aq[i] = idx & 3; }
    #pragma unroll
    for (int i = 0; i < 2; i++) { int idx = t + i * 256; brow[i] = idx >> 5; bq[i] = idx & 31; }

    float4 pa[4], pb[2];

    // Stage k-tile 0
    #pragma unroll
    for (int i = 0; i < 4; i++)
        pa[i] = *reinterpret_cast<const float4*>(&A[(size_t)(bm + arow[i]) * K + aq[i] * 4]);
    #pragma unroll
    for (int i = 0; i < 2; i++)
        pb[i] = *reinterpret_cast<const float4*>(&B[(size_t)brow[i] * N + bn + bq[i] * 4]);
    #pragma unroll
    for (int i = 0; i < 4; i++) {
        float4 v = pa[i];
        if (scale) {
            float dd = scale_of(scale, bm + arow[i], aq[i] * 4);
            v.x *= dd; v.y *= dd; v.z *= dd; v.w *= dd;
        }
        *reinterpret_cast<float4*>(&As[arow[i] * ASTR + aq[i] * 4]) = tf4(v);
    }
    #pragma unroll
    for (int i = 0; i < 2; i++)
        *reinterpret_cast<float4*>(&Bs[brow[i] * BSTR + bq[i] * 4]) = tf4(pb[i]);
    __syncthreads();

    const int KT = K / GBK;
    for (int kt = 0; kt < KT; kt++) {
        int k0n = (kt + 1) * GBK;
        if (kt + 1 < KT) {
            #pragma unroll
            for (int i = 0; i < 4; i++)
                pa[i] = *reinterpret_cast<const float4*>(&A[(size_t)(bm + arow[i]) * K + k0n + aq[i] * 4]);
            #pragma unroll
            for (int i = 0; i < 2; i++)
                pb[i] = *reinterpret_cast<const float4*>(&B[(size_t)(k0n + brow[i]) * N + bn + bq[i] * 4]);
        }

        #pragma unroll
        for (int kk = 0; kk < 2; kk++) {
            const int kb = kk * 8;
            uint32_t af[4][4], bf[8][2];
            #pragma unroll
            for (int mt = 0; mt < 4; mt++) {
                int rb = wm * 64 + mt * 16;
                af[mt][0] = __float_as_uint(As[(rb + r) * ASTR + kb + cq]);
                af[mt][1] = __float_as_uint(As[(rb + 8 + r) * ASTR + kb + cq]);
                af[mt][2] = __float_as_uint(As[(rb + r) * ASTR + kb + 4 + cq]);
                af[mt][3] = __float_as_uint(As[(rb + 8 + r) * ASTR + kb + 4 + cq]);
            }
            #pragma unroll
            for (int nt = 0; nt < 8; nt++) {
                int cb = wn * 64 + nt * 8 + r;
                bf[nt][0] = __float_as_uint(Bs[(kb + cq) * BSTR + cb]);
                bf[nt][1] = __float_as_uint(Bs[(kb + 4 + cq) * BSTR + cb]);
            }
            #pragma unroll
            for (int mt = 0; mt < 4; mt++)
                #pragma unroll
                for (int nt = 0; nt < 8; nt++)
                    mma_tf32(acc[mt][nt], af[mt], bf[nt]);
        }
        __syncthreads();

        if (kt + 1 < KT) {
            #pragma unroll
            for (int i = 0; i < 4; i++) {
                float4 v = pa[i];
                if (scale) {
                    float dd = scale_of(scale, bm + arow[i], k0n + aq[i] * 4);
                    v.x *= dd; v.y *= dd; v.z *= dd; v.w *= dd;
                }
                *reinterpret_cast<float4*>(&As[arow[i] * ASTR + aq[i] * 4]) = tf4(v);
            }
            #pragma unroll
            for (int i = 0; i < 2; i++)
                *reinterpret_cast<float4*>(&Bs[brow[i] * BSTR + bq[i] * 4]) = tf4(pb[i]);
        }
        __syncthreads();
    }

    // Epilogue with bias
    #pragma unroll
    for (int mt = 0; mt < 4; mt++) {
        int row0 = bm + wm * 64 + mt * 16 + r;
        #pragma unroll
        for (int nt = 0; nt < 8; nt++) {
            int col = bn + wn * 64 + nt * 8 + cq * 2;
            float b0 = bias[col], b1 = bias[col + 1];
            float2 v0 = make_float2(acc[mt][nt][0] + b0, acc[mt][nt][1] + b1);
            float2 v1 = make_float2(acc[mt][nt][2] + b0, acc[mt][nt][3] + b1);
            *reinterpret_cast<float2*>(&C[(size_t)row0 * N + col]) = v0;
            *reinterpret_cast<float2*>(&C[(size_t)(row0 + 8) * N + col]) = v1;
        }
    }
}

// Fused Q/K/V projection: blockIdx.z selects weight/bias/output.
__global__ __launch_bounds__(256, 1) void gemm_qkv(
    const float* __restrict__ X,
    const float* __restrict__ Wq, const float* __restrict__ Wk, const float* __restrict__ Wv,
    const float* __restrict__ bq, const float* __restrict__ bk, const float* __restrict__ bv,
    float* __restrict__ Q, float* __restrict__ K, float* __restrict__ V)
{
    const int z = blockIdx.z;
    const float* B    = (z == 0) ? Wq : (z == 1) ? Wk : Wv;
    const float* bias = (z == 0) ? bq : (z == 1) ? bk : bv;
    float*       C    = (z == 0) ? Q  : (z == 1) ? K  : V;
    gemm_body(X, B, bias, C, nullptr, HID, EE,
              blockIdx.y * GBM, blockIdx.x * GBN);
}

// O projection with fused diag scaling of A (=V).
__global__ __launch_bounds__(256, 1) void gemm_o(
    const float* __restrict__ V, const float* __restrict__ Wo,
    const float* __restrict__ bo, float* __restrict__ C,
    const float* __restrict__ diag)
{
    gemm_body(V, Wo, bo, C, diag, HID, HID,
              blockIdx.y * GBM, blockIdx.x * GBN);
}

// ---------------------------------------------------------------------------
// Score kernel, split over row blocks. Block (cb, rb, p):
//   S = Q[rb-tile] @ K[cb-tile]^T (128x128x64, tf32 mma), e = exp(S/1024),
//   column partial sums -> g_part[rb][p][col]; diag captured when rb==cb.
// 8 warps (4a x 2b), warp tile 32(a) x 64(b).
// ---------------------------------------------------------------------------
#define SSTR 68

__global__ __launch_bounds__(256, 2) void score_diag_tc(
    const float* __restrict__ Q, const float* __restrict__ Km,
    float* __restrict__ diagE, float* __restrict__ partG)
{
    extern __shared__ float sm[];
    float* Ks   = sm;                   // 128 x SSTR
    float* Qs   = sm + 128 * SSTR;      // 128 x SSTR
    float* csum = sm + 2 * 128 * SSTR;  // 128

    const int t    = threadIdx.x;
    const int lane = t & 31, wid = t >> 5;
    const int wm = wid & 3, wn = wid >> 2;
    const int r = lane >> 2, cq = lane & 3;

    const int cb = blockIdx.x;          // column block 0..15
    const int rb = blockIdx.y;          // row block 0..15
    const int p  = blockIdx.z;          // pair 0..63
    const int bn = cb * 128;
    const int a0 = rb * 128;
    const float* Qh = Q  + (size_t)p * LL * DH;
    const float* Kh = Km + (size_t)p * LL * DH;

    // Load K tile (cols) and Q tile (rows), tf32-rounded
    #pragma unroll
    for (int i = 0; i < 8; i++) {
        int idx = t + i * 256;
        int row = idx >> 4, q = idx & 15;
        float4 v = *reinterpret_cast<const float4*>(&Kh[(size_t)(bn + row) * DH + q * 4]);
        *reinterpret_cast<float4*>(&Ks[row * SSTR + q * 4]) = tf4(v);
    }
    #pragma unroll
    for (int i = 0; i < 8; i++) {
        int idx = t + i * 256;
        int row = idx >> 4, q = idx & 15;
        float4 v = *reinterpret_cast<const float4*>(&Qh[(size_t)(a0 + row) * DH + q * 4]);
        *reinterpret_cast<float4*>(&Qs[row * SSTR + q * 4]) = tf4(v);
    }
    __syncthreads();

    float acc[2][8][4];
    #pragma unroll
    for (int mt = 0; mt < 2; mt++)
        #pragma unroll
        for (int nt = 0; nt < 8; nt++)
            #pragma unroll
            for (int j = 0; j < 4; j++) acc[mt][nt][j] = 0.f;

    #pragma unroll
    for (int kk = 0; kk < 8; kk++) {
        const int kb = kk * 8;
        uint32_t af[2][4], bf[8][2];
        #pragma unroll
        for (int mt = 0; mt < 2; mt++) {
            int rbm = wm * 32 + mt * 16;
            af[mt][0] = __float_as_uint(Qs[(rbm + r) * SSTR + kb + cq]);
            af[mt][1] = __float_as_uint(Qs[(rbm + 8 + r) * SSTR + kb + cq]);
            af[mt][2] = __float_as_uint(Qs[(rbm + r) * SSTR + kb + 4 + cq]);
            af[mt][3] = __float_as_uint(Qs[(rbm + 8 + r) * SSTR + kb + 4 + cq]);
        }
        #pragma unroll
        for (int nt = 0; nt < 8; nt++) {
            int cbi = wn * 64 + nt * 8 + r;
            bf[nt][0] = __float_as_uint(Ks[cbi * SSTR + kb + cq]);
            bf[nt][1] = __float_as_uint(Ks[cbi * SSTR + kb + 4 + cq]);
        }
        #pragma unroll
        for (int mt = 0; mt < 2; mt++)
            #pragma unroll
            for (int nt = 0; nt < 8; nt++)
                mma_tf32(acc[mt][nt], af[mt], bf[nt]);
    }

    // exp + per-warp column partials; capture diagonal when rb==cb
    const float S = 1.0f / 1024.0f;
    const bool diagblk = (rb == cb);
    float partial[8][2];
    #pragma unroll
    for (int nt = 0; nt < 8; nt++) { partial[nt][0] = 0.f; partial[nt][1] = 0.f; }

    #pragma unroll
    for (int mt = 0; mt < 2; mt++) {
        int arow0 = wm * 32 + mt * 16 + r;
        #pragma unroll
        for (int nt = 0; nt < 8; nt++) {
            #pragma unroll
            for (int j = 0; j < 2; j++) {
                int bcol = wn * 64 + nt * 8 + cq * 2 + j;
                float e0 = __expf(acc[mt][nt][j] * S);
                float e1 = __expf(acc[mt][nt][2 + j] * S);
                partial[nt][j] += e0 + e1;
                if (diagblk) {
                    if (arow0 == bcol)     diagE[(size_t)p * LL + bn + bcol] = e0;
                    if (arow0 + 8 == bcol) diagE[(size_t)p * LL + bn + bcol] = e1;
                }
            }
        }
    }

    // Reduce partials over the 8 row-groups within the warp
    #pragma unroll
    for (int nt = 0; nt < 8; nt++)
        #pragma unroll
        for (int j = 0; j < 2; j++) {
            float v = partial[nt][j];
            v += __shfl_xor_sync(0xFFFFFFFF, v, 4);
            v += __shfl_xor_sync(0xFFFFFFFF, v, 8);
            v += __shfl_xor_sync(0xFFFFFFFF, v, 16);
            partial[nt][j] = v;
        }

    if (t < 128) csum[t] = 0.f;
    __syncthreads();
    if (r == 0) {
        #pragma unroll
        for (int nt = 0; nt < 8; nt++)
            #pragma unroll
            for (int j = 0; j < 2; j++)
                atomicAdd(&csum[wn * 64 + nt * 8 + cq * 2 + j], partial[nt][j]);
    }
    __syncthreads();
    if (t < 128)
        partG[((size_t)rb * NPAIR + p) * LL + bn + t] = csum[t];
}

// ---------------------------------------------------------------------------
// diag[p][c] = diagE[p][c] / sum_rb part[rb][p][c]
// ---------------------------------------------------------------------------
__global__ __launch_bounds__(256) void divide_kernel(
    const float* __restrict__ diagE, const float* __restrict__ part,
    float* __restrict__ diag)
{
    int i = blockIdx.x * 256 + threadIdx.x;           // over NPAIR*LL
    if (i >= NPAIR * LL) return;
    float s = 0.f;
    #pragma unroll
    for (int rb = 0; rb < RBLK; rb++)
        s += part[(size_t)rb * NPAIR * LL + i];
    diag[i] = diagE[i] / s;
}

// ---------------------------------------------------------------------------
extern "C" void kernel_launch(void* const* d_in, const int* in_sizes, int n_in,
                              void* d_out, int out_size)
{
    const float* X  = (const float*)d_in[0];
    const float* Wq = (const float*)d_in[1];
    const float* bq = (const float*)d_in[2];
    const float* Wk = (const float*)d_in[3];
    const float* bk = (const float*)d_in[4];
    const float* Wv = (const float*)d_in[5];
    const float* bv = (const float*)d_in[6];
    const float* Wo = (const float*)d_in[7];
    const float* bo = (const float*)d_in[8];
    float* out = (float*)d_out;

    float *Q, *K, *V, *dgE, *pt, *dg;
    cudaGetSymbolAddress((void**)&Q,   g_Q);
    cudaGetSymbolAddress((void**)&K,   g_K);
    cudaGetSymbolAddress((void**)&V,   g_V);
    cudaGetSymbolAddress((void**)&dgE, g_diagE);
    cudaGetSymbolAddress((void**)&pt,  g_part);
    cudaGetSymbolAddress((void**)&dg,  g_diag);

    const int score_smem = (2 * 128 * SSTR + 128) * sizeof(float);
    static int attr_done = 0;
    if (!attr_done) {
        cudaFuncSetAttribute(score_diag_tc,
                             cudaFuncAttributeMaxDynamicSharedMemorySize, score_smem);
        attr_done = 1;
    }

    dim3 qkv_grid(HID / GBN, MROWS / GBM, 3);   // (8, 32, 3) = 768 blocks
    gemm_qkv<<<qkv_grid, 256>>>(X, Wq, Wk, Wv, bq, bk, bv, Q, K, V);

    dim3 sgrid(LL / 128, RBLK, NPAIR);          // (16, 16, 64)
    score_diag_tc<<<sgrid, 256, score_smem>>>(Q, K, dgE, pt);

    divide_kernel<<<(NPAIR * LL + 255) / 256, 256>>>(dgE, pt, dg);

    dim3 ogrid(HID / GBN, MROWS / GBM);         // (8, 32)
    gemm_o<<<ogrid, 256>>>(V, Wo, bo, out, dg);
}

// round 8
// speedup vs baseline: 3.2557x; 1.0540x over previous
#include <cuda_runtime.h>
#include <cstdint>

// Problem constants
#define NB    4
#define LL    2048
#define EE    1024
#define HID   1024
#define HEADS 16
#define DH    64
#define MROWS 8192
#define NPAIR 64
#define RBLK  16            // row-blocks in score kernel (2048/128)

// Scratch (static device globals)
__device__ float g_Q[MROWS * HID];
__device__ float g_K[MROWS * HID];
__device__ float g_V[MROWS * HID];
__device__ float g_diagE[NPAIR * LL];
__device__ float g_part[RBLK * NPAIR * LL];   // per-rowblock column partial sums
__device__ float g_diag[NPAIR * LL];          // final diagE / colsum

// ---------------------------------------------------------------------------
__device__ __forceinline__ uint32_t f2tf32(float x) {
    uint32_t r;
    asm("cvt.rna.tf32.f32 %0, %1;" : "=r"(r) : "f"(x));
    return r;
}

__device__ __forceinline__ void mma_tf32(float c[4], const uint32_t a[4], const uint32_t b[2]) {
    asm volatile(
        "mma.sync.aligned.m16n8k8.row.col.f32.tf32.tf32.f32 "
        "{%0,%1,%2,%3}, {%4,%5,%6,%7}, {%8,%9}, {%0,%1,%2,%3};\n"
        : "+f"(c[0]), "+f"(c[1]), "+f"(c[2]), "+f"(c[3])
        : "r"(a[0]), "r"(a[1]), "r"(a[2]), "r"(a[3]), "r"(b[0]), "r"(b[1]));
}

__device__ __forceinline__ float4 tf4(float4 v) {
    float4 w;
    w.x = __uint_as_float(f2tf32(v.x));
    w.y = __uint_as_float(f2tf32(v.y));
    w.z = __uint_as_float(f2tf32(v.z));
    w.w = __uint_as_float(f2tf32(v.w));
    return w;
}

// ---------------------------------------------------------------------------
// Tensor-core GEMM body: C[M,N] = (scale ? diag-scaled A : A)[M,K] @ B + bias.
// Block tile 128x128, BK=16, 8 warps (4m x 2n), warp tile 32x64.
// Double-buffered smem, one __syncthreads per k-tile, 2 CTAs/SM.
// ---------------------------------------------------------------------------
#define GBM 128
#define GBN 128
#define GBK 16
#define ASTR 20
#define BSTR 136
#define ASZ (GBM * ASTR)   // 2560 floats
#define BSZ (GBK * BSTR)   // 2176 floats

__device__ __forceinline__ float scale_of(const float* scale, int row, int k) {
    int lr = row & (LL - 1);
    int n  = row >> 11;
    int h  = lr >> 7;
    int a  = ((lr & 127) << 4) | (k >> 6);
    return scale[((size_t)(n * HEADS + h)) * LL + a];
}

__device__ __forceinline__ void gemm_body(
    const float* __restrict__ A, const float* __restrict__ B,
    const float* __restrict__ bias, float* __restrict__ C,
    const float* __restrict__ scale, int N, int K, int bm, int bn)
{
    __shared__ float As[2 * ASZ];
    __shared__ float Bs[2 * BSZ];

    const int t    = threadIdx.x;
    const int lane = t & 31, wid = t >> 5;
    const int wm = wid & 3, wn = wid >> 2;
    const int r = lane >> 2, cq = lane & 3;

    float acc[2][8][4];
    #pragma unroll
    for (int mt = 0; mt < 2; mt++)
        #pragma unroll
        for (int nt = 0; nt < 8; nt++)
            #pragma unroll
            for (int j = 0; j < 4; j++) acc[mt][nt][j] = 0.f;

    // Per-thread staging coordinates: A tile 128x16 (2 float4/thread),
    // B tile 16x128 (2 float4/thread).
    int arow[2], aq[2], brow[2], bq[2];
    #pragma unroll
    for (int i = 0; i < 2; i++) {
        int idx = t + i * 256;
        arow[i] = idx >> 2;  aq[i] = idx & 3;      // A: row 0..127, kq 0..3
        brow[i] = idx >> 5;  bq[i] = idx & 31;     // B: k 0..15, nq 0..31
    }

    float4 pa[2], pb[2];

    // Stage k-tile 0 into buffer 0
    #pragma unroll
    for (int i = 0; i < 2; i++) {
        pa[i] = *reinterpret_cast<const float4*>(&A[(size_t)(bm + arow[i]) * K + aq[i] * 4]);
        pb[i] = *reinterpret_cast<const float4*>(&B[(size_t)brow[i] * N + bn + bq[i] * 4]);
    }
    #pragma unroll
    for (int i = 0; i < 2; i++) {
        float4 v = pa[i];
        if (scale) {
            float dd = scale_of(scale, bm + arow[i], aq[i] * 4);
            v.x *= dd; v.y *= dd; v.z *= dd; v.w *= dd;
        }
        *reinterpret_cast<float4*>(&As[arow[i] * ASTR + aq[i] * 4]) = tf4(v);
        *reinterpret_cast<float4*>(&Bs[brow[i] * BSTR + bq[i] * 4]) = tf4(pb[i]);
    }
    __syncthreads();

    const int KT = K / GBK;
    for (int kt = 0; kt < KT; kt++) {
        const int b = kt & 1;
        const float* Asb = &As[b * ASZ];
        const float* Bsb = &Bs[b * BSZ];
        const int k0n = (kt + 1) * GBK;

        if (kt + 1 < KT) {
            #pragma unroll
            for (int i = 0; i < 2; i++) {
                pa[i] = *reinterpret_cast<const float4*>(&A[(size_t)(bm + arow[i]) * K + k0n + aq[i] * 4]);
                pb[i] = *reinterpret_cast<const float4*>(&B[(size_t)(k0n + brow[i]) * N + bn + bq[i] * 4]);
            }
        }

        #pragma unroll
        for (int kk = 0; kk < 2; kk++) {
            const int kb = kk * 8;
            uint32_t af[2][4], bf[8][2];
            #pragma unroll
            for (int mt = 0; mt < 2; mt++) {
                int rb = wm * 32 + mt * 16;
                af[mt][0] = __float_as_uint(Asb[(rb + r) * ASTR + kb + cq]);
                af[mt][1] = __float_as_uint(Asb[(rb + 8 + r) * ASTR + kb + cq]);
                af[mt][2] = __float_as_uint(Asb[(rb + r) * ASTR + kb + 4 + cq]);
                af[mt][3] = __float_as_uint(Asb[(rb + 8 + r) * ASTR + kb + 4 + cq]);
            }
            #pragma unroll
            for (int nt = 0; nt < 8; nt++) {
                int cb = wn * 64 + nt * 8 + r;
                bf[nt][0] = __float_as_uint(Bsb[(kb + cq) * BSTR + cb]);
                bf[nt][1] = __float_as_uint(Bsb[(kb + 4 + cq) * BSTR + cb]);
            }
            #pragma unroll
            for (int mt = 0; mt < 2; mt++)
                #pragma unroll
                for (int nt = 0; nt < 8; nt++)
                    mma_tf32(acc[mt][nt], af[mt], bf[nt]);
        }

        if (kt + 1 < KT) {
            float* Asn = &As[(1 - b) * ASZ];
            float* Bsn = &Bs[(1 - b) * BSZ];
            #pragma unroll
            for (int i = 0; i < 2; i++) {
                float4 v = pa[i];
                if (scale) {
                    float dd = scale_of(scale, bm + arow[i], k0n + aq[i] * 4);
                    v.x *= dd; v.y *= dd; v.z *= dd; v.w *= dd;
                }
                *reinterpret_cast<float4*>(&Asn[arow[i] * ASTR + aq[i] * 4]) = tf4(v);
                *reinterpret_cast<float4*>(&Bsn[brow[i] * BSTR + bq[i] * 4]) = tf4(pb[i]);
            }
        }
        __syncthreads();
    }

    // Epilogue with bias
    #pragma unroll
    for (int mt = 0; mt < 2; mt++) {
        int row0 = bm + wm * 32 + mt * 16 + r;
        #pragma unroll
        for (int nt = 0; nt < 8; nt++) {
            int col = bn + wn * 64 + nt * 8 + cq * 2;
            float b0 = bias[col], b1 = bias[col + 1];
            float2 v0 = make_float2(acc[mt][nt][0] + b0, acc[mt][nt][1] + b1);
            float2 v1 = make_float2(acc[mt][nt][2] + b0, acc[mt][nt][3] + b1);
            *reinterpret_cast<float2*>(&C[(size_t)row0 * N + col]) = v0;
            *reinterpret_cast<float2*>(&C[(size_t)(row0 + 8) * N + col]) = v1;
        }
    }
}

// Fused Q/K/V projection: blockIdx.z selects weight/bias/output.
__global__ __launch_bounds__(256, 2) void gemm_qkv(
    const float* __restrict__ X,
    const float* __restrict__ Wq, const float* __restrict__ Wk, const float* __restrict__ Wv,
    const float* __restrict__ bq, const float* __restrict__ bk, const float* __restrict__ bv,
    float* __restrict__ Q, float* __restrict__ K, float* __restrict__ V)
{
    const int z = blockIdx.z;
    const float* B    = (z == 0) ? Wq : (z == 1) ? Wk : Wv;
    const float* bias = (z == 0) ? bq : (z == 1) ? bk : bv;
    float*       C    = (z == 0) ? Q  : (z == 1) ? K  : V;
    gemm_body(X, B, bias, C, nullptr, HID, EE,
              blockIdx.y * GBM, blockIdx.x * GBN);
}

// O projection with fused diag scaling of A (=V).
__global__ __launch_bounds__(256, 2) void gemm_o(
    const float* __restrict__ V, const float* __restrict__ Wo,
    const float* __restrict__ bo, float* __restrict__ C,
    const float* __restrict__ diag)
{
    gemm_body(V, Wo, bo, C, diag, HID, HID,
              blockIdx.y * GBM, blockIdx.x * GBN);
}

// ---------------------------------------------------------------------------
// Score kernel, split over row blocks. Block (cb, rb, p):
//   S = Q[rb-tile] @ K[cb-tile]^T (128x128x64, tf32 mma), e = exp(S/1024),
//   column partial sums -> g_part[rb][p][col]; diag captured when rb==cb.
// 8 warps (4a x 2b), warp tile 32(a) x 64(b).
// ---------------------------------------------------------------------------
#define SSTR 68

__global__ __launch_bounds__(256, 2) void score_diag_tc(
    const float* __restrict__ Q, const float* __restrict__ Km,
    float* __restrict__ diagE, float* __restrict__ partG)
{
    extern __shared__ float sm[];
    float* Ks   = sm;                   // 128 x SSTR
    float* Qs   = sm + 128 * SSTR;      // 128 x SSTR
    float* csum = sm + 2 * 128 * SSTR;  // 128

    const int t    = threadIdx.x;
    const int lane = t & 31, wid = t >> 5;
    const int wm = wid & 3, wn = wid >> 2;
    const int r = lane >> 2, cq = lane & 3;

    const int cb = blockIdx.x;          // column block 0..15
    const int rb = blockIdx.y;          // row block 0..15
    const int p  = blockIdx.z;          // pair 0..63
    const int bn = cb * 128;
    const int a0 = rb * 128;
    const float* Qh = Q  + (size_t)p * LL * DH;
    const float* Kh = Km + (size_t)p * LL * DH;

    // Load K tile (cols) and Q tile (rows), tf32-rounded
    #pragma unroll
    for (int i = 0; i < 8; i++) {
        int idx = t + i * 256;
        int row = idx >> 4, q = idx & 15;
        float4 v = *reinterpret_cast<const float4*>(&Kh[(size_t)(bn + row) * DH + q * 4]);
        *reinterpret_cast<float4*>(&Ks[row * SSTR + q * 4]) = tf4(v);
    }
    #pragma unroll
    for (int i = 0; i < 8; i++) {
        int idx = t + i * 256;
        int row = idx >> 4, q = idx & 15;
        float4 v = *reinterpret_cast<const float4*>(&Qh[(size_t)(a0 + row) * DH + q * 4]);
        *reinterpret_cast<float4*>(&Qs[row * SSTR + q * 4]) = tf4(v);
    }
    __syncthreads();

    float acc[2][8][4];
    #pragma unroll
    for (int mt = 0; mt < 2; mt++)
        #pragma unroll
        for (int nt = 0; nt < 8; nt++)
            #pragma unroll
            for (int j = 0; j < 4; j++) acc[mt][nt][j] = 0.f;

    #pragma unroll
    for (int kk = 0; kk < 8; kk++) {
        const int kb = kk * 8;
        uint32_t af[2][4], bf[8][2];
        #pragma unroll
        for (int mt = 0; mt < 2; mt++) {
            int rbm = wm * 32 + mt * 16;
            af[mt][0] = __float_as_uint(Qs[(rbm + r) * SSTR + kb + cq]);
            af[mt][1] = __float_as_uint(Qs[(rbm + 8 + r) * SSTR + kb + cq]);
            af[mt][2] = __float_as_uint(Qs[(rbm + r) * SSTR + kb + 4 + cq]);
            af[mt][3] = __float_as_uint(Qs[(rbm + 8 + r) * SSTR + kb + 4 + cq]);
        }
        #pragma unroll
        for (int nt = 0; nt < 8; nt++) {
            int cbi = wn * 64 + nt * 8 + r;
            bf[nt][0] = __float_as_uint(Ks[cbi * SSTR + kb + cq]);
            bf[nt][1] = __float_as_uint(Ks[cbi * SSTR + kb + 4 + cq]);
        }
        #pragma unroll
        for (int mt = 0; mt < 2; mt++)
            #pragma unroll
            for (int nt = 0; nt < 8; nt++)
                mma_tf32(acc[mt][nt], af[mt], bf[nt]);
    }

    // exp + per-warp column partials; capture diagonal when rb==cb
    const float S = 1.0f / 1024.0f;
    const bool diagblk = (rb == cb);
    float partial[8][2];
    #pragma unroll
    for (int nt = 0; nt < 8; nt++) { partial[nt][0] = 0.f; partial[nt][1] = 0.f; }

    #pragma unroll
    for (int mt = 0; mt < 2; mt++) {
        int arow0 = wm * 32 + mt * 16 + r;
        #pragma unroll
        for (int nt = 0; nt < 8; nt++) {
            #pragma unroll
            for (int j = 0; j < 2; j++) {
                int bcol = wn * 64 + nt * 8 + cq * 2 + j;
                float e0 = __expf(acc[mt][nt][j] * S);
                float e1 = __expf(acc[mt][nt][2 + j] * S);
                partial[nt][j] += e0 + e1;
                if (diagblk) {
                    if (arow0 == bcol)     diagE[(size_t)p * LL + bn + bcol] = e0;
                    if (arow0 + 8 == bcol) diagE[(size_t)p * LL + bn + bcol] = e1;
                }
            }
        }
    }

    // Reduce partials over the 8 row-groups within the warp
    #pragma unroll
    for (int nt = 0; nt < 8; nt++)
        #pragma unroll
        for (int j = 0; j < 2; j++) {
            float v = partial[nt][j];
            v += __shfl_xor_sync(0xFFFFFFFF, v, 4);
            v += __shfl_xor_sync(0xFFFFFFFF, v, 8);
            v += __shfl_xor_sync(0xFFFFFFFF, v, 16);
            partial[nt][j] = v;
        }

    if (t < 128) csum[t] = 0.f;
    __syncthreads();
    if (r == 0) {
        #pragma unroll
        for (int nt = 0; nt < 8; nt++)
            #pragma unroll
            for (int j = 0; j < 2; j++)
                atomicAdd(&csum[wn * 64 + nt * 8 + cq * 2 + j], partial[nt][j]);
    }
    __syncthreads();
    if (t < 128)
        partG[((size_t)rb * NPAIR + p) * LL + bn + t] = csum[t];
}

// ---------------------------------------------------------------------------
// diag[p][c] = diagE[p][c] / sum_rb part[rb][p][c]
// ---------------------------------------------------------------------------
__global__ __launch_bounds__(256) void divide_kernel(
    const float* __restrict__ diagE, const float* __restrict__ part,
    float* __restrict__ diag)
{
    int i = blockIdx.x * 256 + threadIdx.x;           // over NPAIR*LL
    if (i >= NPAIR * LL) return;
    float s = 0.f;
    #pragma unroll
    for (int rb = 0; rb < RBLK; rb++)
        s += part[(size_t)rb * NPAIR * LL + i];
    diag[i] = diagE[i] / s;
}

// ---------------------------------------------------------------------------
extern "C" void kernel_launch(void* const* d_in, const int* in_sizes, int n_in,
                              void* d_out, int out_size)
{
    const float* X  = (const float*)d_in[0];
    const float* Wq = (const float*)d_in[1];
    const float* bq = (const float*)d_in[2];
    const float* Wk = (const float*)d_in[3];
    const float* bk = (const float*)d_in[4];
    const float* Wv = (const float*)d_in[5];
    const float* bv = (const float*)d_in[6];
    const float* Wo = (const float*)d_in[7];
    const float* bo = (const float*)d_in[8];
    float* out = (float*)d_out;

    float *Q, *K, *V, *dgE, *pt, *dg;
    cudaGetSymbolAddress((void**)&Q,   g_Q);
    cudaGetSymbolAddress((void**)&K,   g_K);
    cudaGetSymbolAddress((void**)&V,   g_V);
    cudaGetSymbolAddress((void**)&dgE, g_diagE);
    cudaGetSymbolAddress((void**)&pt,  g_part);
    cudaGetSymbolAddress((void**)&dg,  g_diag);

    const int score_smem = (2 * 128 * SSTR + 128) * sizeof(float);
    static int attr_done = 0;
    if (!attr_done) {
        cudaFuncSetAttribute(score_diag_tc,
                             cudaFuncAttributeMaxDynamicSharedMemorySize, score_smem);
        attr_done = 1;
    }

    dim3 qkv_grid(HID / GBN, MROWS / GBM, 3);   // (8, 64, 3) = 1536 blocks
    gemm_qkv<<<qkv_grid, 256>>>(X, Wq, Wk, Wv, bq, bk, bv, Q, K, V);

    dim3 sgrid(LL / 128, RBLK, NPAIR);          // (16, 16, 64)
    score_diag_tc<<<sgrid, 256, score_smem>>>(Q, K, dgE, pt);

    divide_kernel<<<(NPAIR * LL + 255) / 256, 256>>>(dgE, pt, dg);

    dim3 ogrid(HID / GBN, MROWS / GBM);         // (8, 64)
    gemm_o<<<ogrid, 256>>>(V, Wo, bo, out, dg);
}